// round 8
// baseline (speedup 1.0000x reference)
#include <cuda_runtime.h>
#include <cmath>

#define CF 22
#define IPAD 24
#define KPAD 24
#define NM 9
#define TILE_W 16
#define TILE_H 16
#define NT 128
#define NPX 256          // pixels per block (2 per thread)
#define STG_STRIDE 53    // per-pixel stage stride (odd -> conflict-free)
#define SCR_STRIDE 89    // per-thread ctx scratch stride

typedef unsigned long long ull;

__device__ float gWtp[CF * CF * IPAD];  // [k][j][i24]
__device__ float gK[NM * CF * KPAD];    // [m][i][k24]

// ---- packed f32x2 helpers ----
__device__ __forceinline__ ull pk2(float lo, float hi) {
    ull r; asm("mov.b64 %0, {%1,%2};" : "=l"(r) : "f"(lo), "f"(hi)); return r;
}
__device__ __forceinline__ void upk2(ull v, float& a, float& b) {
    asm("mov.b64 {%0,%1}, %2;" : "=f"(a), "=f"(b) : "l"(v));
}
__device__ __forceinline__ ull pdup(float x) {
    ull r; asm("mov.b64 %0, {%1,%1};" : "=l"(r) : "f"(x)); return r;
}
__device__ __forceinline__ ull pfma(ull a, ull b, ull c) {
    ull r; asm("fma.rn.f32x2 %0, %1, %2, %3;" : "=l"(r) : "l"(a), "l"(b), "l"(c)); return r;
}
__device__ __forceinline__ ull pmul(ull a, ull b) {
    ull r; asm("mul.rn.f32x2 %0, %1, %2;" : "=l"(r) : "l"(a), "l"(b)); return r;
}
__device__ __forceinline__ ull padd(ull a, ull b) {
    ull r; asm("add.rn.f32x2 %0, %1, %2;" : "=l"(r) : "l"(a), "l"(b)); return r;
}

// ============================================================================
// Prep (unchanged)
// ============================================================================
__global__ void prep_kernel(const float* __restrict__ sh,
                            const float* __restrict__ cg_agg,
                            const float* __restrict__ cg_tp,
                            const float* __restrict__ w_agg,
                            const float* __restrict__ w_tp) {
    int gtid = blockIdx.x * blockDim.x + threadIdx.x;
    int nthr = gridDim.x * blockDim.x;
    for (int idx = gtid; idx < CF * CF * IPAD; idx += nthr) {
        int k = idx / (CF * IPAD);
        int r = idx - k * CF * IPAD;
        int j = r / IPAD;
        int i = r - j * IPAD;
        float v = 0.f;
        if (i < CF) {
            #pragma unroll
            for (int p = 0; p < 8; p++)
                v += w_tp[p] * cg_tp[((p * CF + i) * CF + j) * CF + k];
        }
        gWtp[idx] = v;
    }
    for (int idx = gtid; idx < CF * KPAD; idx += nthr) {
        int i = idx / KPAD;
        int k = idx - i * KPAD;
        float K0 = 0.f, K1 = 0.f, K2 = 0.f, K3 = 0.f;
        if (k < CF) {
            #pragma unroll
            for (int s = 0; s < 6; s++) {
                float wa = 0.f;
                #pragma unroll
                for (int p = 0; p < 6; p++)
                    wa += w_agg[p] * cg_agg[((p * CF + i) * 6 + s) * CF + k];
                K0 += wa * sh[0 * 6 + s];
                K1 += wa * sh[1 * 6 + s];
                K2 += wa * sh[2 * 6 + s];
                K3 += wa * sh[3 * 6 + s];
            }
        }
        gK[(0 * CF + i) * KPAD + k] = K0 + K1 + K2 + K3;
        gK[(1 * CF + i) * KPAD + k] = K0 + K2;
        gK[(2 * CF + i) * KPAD + k] = K0 + K1;
        gK[(3 * CF + i) * KPAD + k] = K0;
        gK[(4 * CF + i) * KPAD + k] = K1 + K3;
        gK[(5 * CF + i) * KPAD + k] = K1;
        gK[(6 * CF + i) * KPAD + k] = K2 + K3;
        gK[(7 * CF + i) * KPAD + k] = K2;
        gK[(8 * CF + i) * KPAD + k] = K3;
    }
}

// ctx accumulation pass (src = per-thread smem scratch; static ctx2 indices)
template <int CAT>
__device__ __forceinline__ void ctx_pass(ull (&ctx2)[4][11], const ulonglong2* sK2,
                                         const float* src, int m) {
    #pragma unroll 2
    for (int i = 0; i < CF; i++) {
        ull fi2 = pdup(src[i]);
        const ulonglong2* row = sK2 + (m * CF + i) * 6;
        #pragma unroll
        for (int c = 0; c < 5; c++) {
            ulonglong2 t = row[c];
            ctx2[CAT][2 * c]     = pfma(fi2, t.x, ctx2[CAT][2 * c]);
            ctx2[CAT][2 * c + 1] = pfma(fi2, t.y, ctx2[CAT][2 * c + 1]);
        }
        ull t10 = row[5].x;
        ctx2[CAT][10] = pfma(fi2, t10, ctx2[CAT][10]);
    }
}

// ctx for one pixel: passes over K, write ctxS[j][px][4cats], self -> f2 regs
__device__ __forceinline__ void compute_ctx_px(
    const float* __restrict__ f4, const float* __restrict__ f6, int H, int W,
    int h0, int w0, const ulonglong2* sK2, float* scr, float* ctxS, int px,
    ull (&f2)[11]) {
    const int wR = min(w0 + 1, W - 1);
    const int hD = min(h0 + 1, H - 1);
    const int p00 = h0 * W + w0;
    const int p01 = h0 * W + wR;
    const int p10 = hD * W + w0;
    const int p11 = hD * W + wR;
    {
        float xv[CF];
        #pragma unroll
        for (int c = 0; c < 9; c++) xv[c] = f4[p00 * 9 + c];
        #pragma unroll
        for (int c = 0; c < 13; c++) xv[9 + c] = f6[p00 * 13 + c];
        #pragma unroll
        for (int kk = 0; kk < 11; kk++) {
            f2[kk] = pk2(xv[2 * kk], xv[2 * kk + 1]);
            scr[2 * kk] = xv[2 * kk];
            scr[2 * kk + 1] = xv[2 * kk + 1];
        }
        #pragma unroll
        for (int c = 0; c < 9; c++) {
            scr[1 * CF + c] = f4[p01 * 9 + c];
            scr[2 * CF + c] = f4[p10 * 9 + c];
            scr[3 * CF + c] = f4[p11 * 9 + c];
        }
        #pragma unroll
        for (int c = 0; c < 13; c++) {
            scr[1 * CF + 9 + c] = f6[p01 * 13 + c];
            scr[2 * CF + 9 + c] = f6[p10 * 13 + c];
            scr[3 * CF + 9 + c] = f6[p11 * 13 + c];
        }
    }
    ull ctx2[4][11];
    #pragma unroll
    for (int c4 = 0; c4 < 4; c4++)
        #pragma unroll
        for (int kk = 0; kk < 11; kk++) ctx2[c4][kk] = 0ULL;

    ctx_pass<0>(ctx2, sK2, scr, 0);
    ctx_pass<1>(ctx2, sK2, scr, 1);
    ctx_pass<2>(ctx2, sK2, scr, 2);
    ctx_pass<3>(ctx2, sK2, scr, 3);
    ctx_pass<1>(ctx2, sK2, scr + CF, 4);
    ctx_pass<3>(ctx2, sK2, scr + CF, 5);
    ctx_pass<2>(ctx2, sK2, scr + 2 * CF, 6);
    ctx_pass<3>(ctx2, sK2, scr + 2 * CF, 7);
    ctx_pass<3>(ctx2, sK2, scr + 3 * CF, 8);

    #pragma unroll
    for (int kk = 0; kk < 11; kk++) {
        float a0, b0, a1, b1, a2, b2, a3, b3;
        upk2(ctx2[0][kk], a0, b0);
        upk2(ctx2[1][kk], a1, b1);
        upk2(ctx2[2][kk], a2, b2);
        upk2(ctx2[3][kk], a3, b3);
        *(float4*)(ctxS + ((2 * kk) * NPX + px) * 4)     = make_float4(a0, a1, a2, a3);
        *(float4*)(ctxS + ((2 * kk + 1) * NPX + px) * 4) = make_float4(b0, b1, b2, b3);
    }
}

// v[k,j] = sum_i f_i * W[k][j][i], returned duplicated into both lanes
__device__ __forceinline__ ull dotv(const ull (&f2)[11], const ulonglong2* wr) {
    ulonglong2 t0 = wr[0], t1 = wr[1], t2 = wr[2];
    ull va = pmul(f2[0], t0.x);
    ull vb = pmul(f2[1], t0.y);
    va = pfma(f2[2], t1.x, va);
    vb = pfma(f2[3], t1.y, vb);
    va = pfma(f2[4], t2.x, va);
    vb = pfma(f2[5], t2.y, vb);
    ulonglong2 t3 = wr[3], t4 = wr[4];
    ull t10 = wr[5].x;
    va = pfma(f2[6], t3.x, va);
    vb = pfma(f2[7], t3.y, vb);
    va = pfma(f2[8], t4.x, va);
    vb = pfma(f2[9], t4.y, vb);
    va = pfma(f2[10], t10, va);
    ull vp = padd(va, vb);
    float a, b;
    upk2(vp, a, b);
    return pdup(a + b);
}

// bilinear phase over k-range [KB, KB+KC): j-outer (ctx amortized), k fully
// unrolled (accumulators statically indexed). W loads shared by both pixels.
template <int KB, int KC>
__device__ __forceinline__ void bil_phase(const ulonglong2* sW2, const float* ctxS,
                                          const ull (&f2A)[11], const ull (&f2B)[11],
                                          int pxA, int pxB, float* stage) {
    ull oA01[KC], oA23[KC], oB01[KC], oB23[KC];
    #pragma unroll
    for (int kk = 0; kk < KC; kk++) {
        oA01[kk] = 0ULL; oA23[kk] = 0ULL; oB01[kk] = 0ULL; oB23[kk] = 0ULL;
    }
    #pragma unroll 1
    for (int j = 0; j < CF; j++) {
        float4 cAv = *(const float4*)(ctxS + (j * NPX + pxA) * 4);
        float4 cBv = *(const float4*)(ctxS + (j * NPX + pxB) * 4);
        ull cA01 = pk2(cAv.x, cAv.y), cA23 = pk2(cAv.z, cAv.w);
        ull cB01 = pk2(cBv.x, cBv.y), cB23 = pk2(cBv.z, cBv.w);
        #pragma unroll
        for (int kk = 0; kk < KC; kk++) {
            const ulonglong2* wr = sW2 + ((KB + kk) * CF + j) * 6;
            ull vdA = dotv(f2A, wr);
            ull vdB = dotv(f2B, wr);   // W loads CSE'd with vdA's
            oA01[kk] = pfma(vdA, cA01, oA01[kk]);
            oA23[kk] = pfma(vdA, cA23, oA23[kk]);
            oB01[kk] = pfma(vdB, cB01, oB01[kk]);
            oB23[kk] = pfma(vdB, cB23, oB23[kk]);
        }
    }
    float* mA = stage + pxA * STG_STRIDE;
    float* mB = stage + pxB * STG_STRIDE;
    #pragma unroll
    for (int kk = 0; kk < KC; kk++) {
        float a0, a1, a2, a3;
        upk2(oA01[kk], a0, a1); upk2(oA23[kk], a2, a3);
        mA[0 * KC + kk] = a0; mA[1 * KC + kk] = a1;
        mA[2 * KC + kk] = a2; mA[3 * KC + kk] = a3;
        upk2(oB01[kk], a0, a1); upk2(oB23[kk], a2, a3);
        mB[0 * KC + kk] = a0; mB[1 * KC + kk] = a1;
        mB[2 * KC + kk] = a2; mB[3 * KC + kk] = a3;
    }
}

// ============================================================================
// Main kernel: 16x16 low-res tile, 128 threads, 2 pixels/thread (y-split).
// smem = sW(46.5K) + sK(19K) + ctxS(90K) + stage/scratch(54.3K) = 209.9KB
//   -> 1 block/SM (intentional: kernel is crossbar-throughput-bound, R7
//      proved occupancy doesn't matter; sharing W between 2 px halves bytes).
// ============================================================================
__global__ void __launch_bounds__(NT, 1)
main_kernel(const float* __restrict__ f4, const float* __restrict__ f6,
            float* __restrict__ out, int H, int W) {
    extern __shared__ float smem[];
    float* sW    = smem;                           // 11616
    float* sK    = sW + CF * CF * IPAD;            // 4752
    float* ctxS  = sK + NM * CF * KPAD;            // 22528
    float* stage = ctxS + CF * NPX * 4;            // 13568 (also ctx scratch)
    const int tid = threadIdx.x;

    for (int idx = tid; idx < CF * CF * IPAD; idx += NT) sW[idx] = gWtp[idx];
    for (int idx = tid; idx < NM * CF * KPAD; idx += NT) sK[idx] = gK[idx];
    __syncthreads();

    const int tiles_x = W / TILE_W;
    const int tx0 = (blockIdx.x % tiles_x) * TILE_W;
    const int ty0 = (blockIdx.x / tiles_x) * TILE_H;
    const int lx = tid % TILE_W;
    const int ly = tid / TILE_W;          // 0..7
    const int pxA = tid;                  // (ly, lx)
    const int pxB = tid + NT;             // (ly+8, lx)

    // ---- ctx phase (scratch lives in the stage region; per-thread private) ----
    float* scr = stage + tid * SCR_STRIDE;
    const ulonglong2* sK2 = (const ulonglong2*)sK;
    ull f2A[11], f2B[11];
    compute_ctx_px(f4, f6, H, W, ty0 + ly,     tx0 + lx, sK2, scr, ctxS, pxA, f2A);
    compute_ctx_px(f4, f6, H, W, ty0 + ly + 8, tx0 + lx, sK2, scr, ctxS, pxB, f2B);
    __syncthreads();  // scratch dead; stage region now safe for staging

    const ulonglong2* sW2 = (const ulonglong2*)sW;
    const int Wr = W * 4;

    // ================= phase 1: k = 0..8 -> out4 =================
    bil_phase<0, 9>(sW2, ctxS, f2A, f2B, pxA, pxB, stage);
    __syncthreads();
    {
        const int QR = TILE_W * 4 * 9 / 4;  // 144 float4 per hi-res row
        for (int idx = tid; idx < TILE_H * 4 * QR; idx += NT) {
            int y = idx / QR;
            int q = idx - y * QR;
            int a = y & 3;
            int py = y >> 2;
            int e = q * 4;
            float4 v;
            float* vv = (float*)&v;
            #pragma unroll
            for (int t = 0; t < 4; t++) {
                int ee = e + t;
                int px = ee / 9;
                int c = ee - px * 9;
                int b = px & 3;
                int lxr = px >> 2;
                int cat = (a < 3) ? ((b < 3) ? 0 : 1) : ((b < 3) ? 2 : 3);
                vv[t] = stage[(py * TILE_W + lxr) * STG_STRIDE + cat * 9 + c]
                      + f4[(size_t)((ty0 + py) * W + tx0 + lxr) * 9 + c];
            }
            int gy = ty0 * 4 + y;
            float4* dst = (float4*)(out + ((size_t)gy * Wr + (size_t)tx0 * 4) * 9);
            dst[q] = v;
        }
    }
    __syncthreads();

    // ================= phase 2: k = 9..21 -> out6 =================
    bil_phase<9, 13>(sW2, ctxS, f2A, f2B, pxA, pxB, stage);
    __syncthreads();
    {
        const size_t N9 = (size_t)H * W * 16 * 9;
        const int QR = TILE_W * 4 * 13 / 4;  // 208 float4 per hi-res row
        for (int idx = tid; idx < TILE_H * 4 * QR; idx += NT) {
            int y = idx / QR;
            int q = idx - y * QR;
            int a = y & 3;
            int py = y >> 2;
            int e = q * 4;
            float4 v;
            float* vv = (float*)&v;
            #pragma unroll
            for (int t = 0; t < 4; t++) {
                int ee = e + t;
                int px = ee / 13;
                int c = ee - px * 13;
                int b = px & 3;
                int lxr = px >> 2;
                int cat = (a < 3) ? ((b < 3) ? 0 : 1) : ((b < 3) ? 2 : 3);
                vv[t] = stage[(py * TILE_W + lxr) * STG_STRIDE + cat * 13 + c]
                      + f6[(size_t)((ty0 + py) * W + tx0 + lxr) * 13 + c];
            }
            int gy = ty0 * 4 + y;
            float4* dst = (float4*)(out + N9 + ((size_t)gy * Wr + (size_t)tx0 * 4) * 13);
            dst[q] = v;
        }
    }
}

extern "C" void kernel_launch(void* const* d_in, const int* in_sizes, int n_in,
                              void* d_out, int out_size) {
    const float* f4     = (const float*)d_in[0];
    const float* f6     = (const float*)d_in[1];
    const float* sh     = (const float*)d_in[2];
    const float* cg_agg = (const float*)d_in[3];
    const float* cg_tp  = (const float*)d_in[4];
    const float* w_agg  = (const float*)d_in[5];
    const float* w_tp   = (const float*)d_in[6];
    float* out = (float*)d_out;

    int HW = in_sizes[0] / 9;
    int W = (int)(sqrt((double)HW) + 0.5);
    int H = HW / W;

    prep_kernel<<<96, 128>>>(sh, cg_agg, cg_tp, w_agg, w_tp);

    int smemFloats = CF * CF * IPAD + NM * CF * KPAD + CF * NPX * 4 + NPX * STG_STRIDE;
    int smemB = smemFloats * (int)sizeof(float);   // 209,856 B
    cudaFuncSetAttribute(main_kernel, cudaFuncAttributeMaxDynamicSharedMemorySize, smemB);
    int nblocks = (W / TILE_W) * (H / TILE_H);
    main_kernel<<<nblocks, NT, smemB>>>(f4, f6, out, H, W);
}

// round 9
// speedup vs baseline: 1.4986x; 1.4986x over previous
#include <cuda_runtime.h>
#include <cmath>

#define CF 22
#define IPAD 24
#define KPAD 24
#define NM 9
#define TILE_W 16
#define TILE_H 8
#define NT 128

typedef unsigned long long ull;

// Precomputed weighted tensors (prep kernel output)
__device__ float gWtp[CF * CF * IPAD];  // [k][j][i24]
__device__ float gK[NM * CF * KPAD];    // [m][i][k24]

// ---- packed f32x2 helpers (Blackwell FFMA2 path; only reachable via PTX) ----
__device__ __forceinline__ ull pk2(float lo, float hi) {
    ull r; asm("mov.b64 %0, {%1,%2};" : "=l"(r) : "f"(lo), "f"(hi)); return r;
}
__device__ __forceinline__ void upk2(ull v, float& a, float& b) {
    asm("mov.b64 {%0,%1}, %2;" : "=f"(a), "=f"(b) : "l"(v));
}
__device__ __forceinline__ ull pdup(float x) {
    ull r; asm("mov.b64 %0, {%1,%1};" : "=l"(r) : "f"(x)); return r;
}
__device__ __forceinline__ ull pfma(ull a, ull b, ull c) {
    ull r; asm("fma.rn.f32x2 %0, %1, %2, %3;" : "=l"(r) : "l"(a), "l"(b), "l"(c)); return r;
}
__device__ __forceinline__ ull pmul(ull a, ull b) {
    ull r; asm("mul.rn.f32x2 %0, %1, %2;" : "=l"(r) : "l"(a), "l"(b)); return r;
}
__device__ __forceinline__ ull padd(ull a, ull b) {
    ull r; asm("add.rn.f32x2 %0, %1, %2;" : "=l"(r) : "l"(a), "l"(b)); return r;
}

// ============================================================================
// Prep: fold learned weights into Wtp and the 9 context matrices.
// m: 0:K0+K1+K2+K3  1:K0+K2  2:K0+K1  3:K0  4:K1+K3  5:K1  6:K2+K3  7:K2  8:K3
// ============================================================================
__global__ void prep_kernel(const float* __restrict__ sh,
                            const float* __restrict__ cg_agg,
                            const float* __restrict__ cg_tp,
                            const float* __restrict__ w_agg,
                            const float* __restrict__ w_tp) {
    int gtid = blockIdx.x * blockDim.x + threadIdx.x;
    int nthr = gridDim.x * blockDim.x;
    for (int idx = gtid; idx < CF * CF * IPAD; idx += nthr) {
        int k = idx / (CF * IPAD);
        int r = idx - k * CF * IPAD;
        int j = r / IPAD;
        int i = r - j * IPAD;
        float v = 0.f;
        if (i < CF) {
            #pragma unroll
            for (int p = 0; p < 8; p++)
                v += w_tp[p] * cg_tp[((p * CF + i) * CF + j) * CF + k];
        }
        gWtp[idx] = v;
    }
    for (int idx = gtid; idx < CF * KPAD; idx += nthr) {
        int i = idx / KPAD;
        int k = idx - i * KPAD;
        float K0 = 0.f, K1 = 0.f, K2 = 0.f, K3 = 0.f;
        if (k < CF) {
            #pragma unroll
            for (int s = 0; s < 6; s++) {
                float wa = 0.f;
                #pragma unroll
                for (int p = 0; p < 6; p++)
                    wa += w_agg[p] * cg_agg[((p * CF + i) * 6 + s) * CF + k];
                K0 += wa * sh[0 * 6 + s];
                K1 += wa * sh[1 * 6 + s];
                K2 += wa * sh[2 * 6 + s];
                K3 += wa * sh[3 * 6 + s];
            }
        }
        gK[(0 * CF + i) * KPAD + k] = K0 + K1 + K2 + K3;
        gK[(1 * CF + i) * KPAD + k] = K0 + K2;
        gK[(2 * CF + i) * KPAD + k] = K0 + K1;
        gK[(3 * CF + i) * KPAD + k] = K0;
        gK[(4 * CF + i) * KPAD + k] = K1 + K3;
        gK[(5 * CF + i) * KPAD + k] = K1;
        gK[(6 * CF + i) * KPAD + k] = K2 + K3;
        gK[(7 * CF + i) * KPAD + k] = K2;
        gK[(8 * CF + i) * KPAD + k] = K3;
    }
}

// Context accumulation pass: ctx2[CAT][*] += src[i] * sK[m][i][*]
template <int CAT>
__device__ __forceinline__ void ctx_pass(ull (&ctx2)[4][11], const ulonglong2* sK2,
                                         const float* src, int m) {
    #pragma unroll 2
    for (int i = 0; i < CF; i++) {
        ull fi2 = pdup(src[i]);
        const ulonglong2* row = sK2 + (m * CF + i) * 6;
        #pragma unroll
        for (int c = 0; c < 5; c++) {
            ulonglong2 t = row[c];
            ctx2[CAT][2 * c]     = pfma(fi2, t.x, ctx2[CAT][2 * c]);
            ctx2[CAT][2 * c + 1] = pfma(fi2, t.y, ctx2[CAT][2 * c + 1]);
        }
        ull t10 = row[5].x;
        ctx2[CAT][10] = pfma(fi2, t10, ctx2[CAT][10]);
    }
}

// ============================================================================
// Main kernel (R5 structure + residual-folded staging + table-driven drain):
//   smem = sW (45.4KB) + sK (18.6KB) + stage (44.5KB) + tables (2.8KB)
//        = 111.2KB -> 2 blocks/SM.
//   Drain has NO divisions and NO global residual loads: the stage already
//   holds tp_out + residual, and a per-block ushort table maps each output
//   element to its stage offset (a==3 rows are the same entry + 44).
// ============================================================================
__global__ void __launch_bounds__(NT, 2)
main_kernel(const float* __restrict__ f4, const float* __restrict__ f6,
            float* __restrict__ out, int H, int W) {
    extern __shared__ float smem[];
    float* sW = smem;                      // CF*CF*IPAD
    float* sK = smem + CF * CF * IPAD;     // NM*CF*KPAD
    float* stg = sK + NM * CF * KPAD;      // NT*89 (stride 89 -> conflict-free)
    unsigned short* tbl4 = (unsigned short*)(stg + NT * 89);  // 576 entries
    unsigned short* tbl6 = tbl4 + 576;                        // 832 entries
    const int tid = threadIdx.x;

    for (int idx = tid; idx < CF * CF * IPAD; idx += NT) sW[idx] = gWtp[idx];
    for (int idx = tid; idx < NM * CF * KPAD; idx += NT) sK[idx] = gK[idx];
    // index tables: stage offset for each element of one hi-res row image
    for (int ee = tid; ee < 576; ee += NT) {
        int px = ee / 9;
        int c = ee - px * 9;
        int b = px & 3;
        int lxr = px >> 2;
        int cat = (b < 3) ? 0 : 1;   // a==3 rows: same entry + 44 (cat 2/3)
        tbl4[ee] = (unsigned short)(lxr * 89 + cat * CF + c);
    }
    for (int ee = tid; ee < 832; ee += NT) {
        int px = ee / 13;
        int c = ee - px * 13;
        int b = px & 3;
        int lxr = px >> 2;
        int cat = (b < 3) ? 0 : 1;
        tbl6[ee] = (unsigned short)(lxr * 89 + cat * CF + 9 + c);
    }
    __syncthreads();

    const int tiles_x = W / TILE_W;
    const int tx0 = (blockIdx.x % tiles_x) * TILE_W;
    const int ty0 = (blockIdx.x / tiles_x) * TILE_H;
    const int lx = tid % TILE_W;
    const int ly = tid / TILE_W;
    const int w0 = tx0 + lx;
    const int h0 = ty0 + ly;
    const int wR = min(w0 + 1, W - 1);
    const int hD = min(h0 + 1, H - 1);
    const int p00 = h0 * W + w0;
    const int p01 = h0 * W + wR;
    const int p10 = hD * W + w0;
    const int p11 = hD * W + wR;

    // ---- preload features: self -> packed regs, all 4 sources -> per-thread stage ----
    float* myst = stg + tid * 89;
    ull f2[11];
    {
        float xv[CF];
        #pragma unroll
        for (int c = 0; c < CF; c++) {
            xv[c] = (c < 9) ? f4[p00 * 9 + c] : f6[p00 * 13 + (c - 9)];
            myst[c] = xv[c];
        }
        #pragma unroll
        for (int kk = 0; kk < 11; kk++) f2[kk] = pk2(xv[2 * kk], xv[2 * kk + 1]);
        #pragma unroll
        for (int c = 0; c < CF; c++) {
            myst[1 * CF + c] = (c < 9) ? f4[p01 * 9 + c] : f6[p01 * 13 + (c - 9)];
            myst[2 * CF + c] = (c < 9) ? f4[p10 * 9 + c] : f6[p10 * 13 + (c - 9)];
            myst[3 * CF + c] = (c < 9) ? f4[p11 * 9 + c] : f6[p11 * 13 + (c - 9)];
        }
    }

    // ---- 4 context vectors (cat 0:interior 1:right-edge 2:bottom-edge 3:corner) ----
    ull ctx2[4][11];
    #pragma unroll
    for (int c4 = 0; c4 < 4; c4++)
        #pragma unroll
        for (int kk = 0; kk < 11; kk++) ctx2[c4][kk] = 0ULL;

    const ulonglong2* sK2 = (const ulonglong2*)sK;
    ctx_pass<0>(ctx2, sK2, myst, 0);
    ctx_pass<1>(ctx2, sK2, myst, 1);
    ctx_pass<2>(ctx2, sK2, myst, 2);
    ctx_pass<3>(ctx2, sK2, myst, 3);
    ctx_pass<1>(ctx2, sK2, myst + CF, 4);
    ctx_pass<3>(ctx2, sK2, myst + CF, 5);
    ctx_pass<2>(ctx2, sK2, myst + 2 * CF, 6);
    ctx_pass<3>(ctx2, sK2, myst + 2 * CF, 7);
    ctx_pass<3>(ctx2, sK2, myst + 3 * CF, 8);

    float ctx[4][CF];
    #pragma unroll
    for (int c4 = 0; c4 < 4; c4++)
        #pragma unroll
        for (int kk = 0; kk < 11; kk++) {
            float a, b;
            upk2(ctx2[c4][kk], a, b);
            ctx[c4][2 * kk] = a;
            ctx[c4][2 * kk + 1] = b;
        }

    // ---- bilinear: out_cat[k] = sum_j ctx[cat][j]*(sum_i f[i]*W[k][j][i]) + f[k] ----
    const ulonglong2* sW2 = (const ulonglong2*)sW;
    #pragma unroll 1
    for (int k = 0; k < CF; k++) {
        ull o0 = 0ULL, o1 = 0ULL, o2a = 0ULL, o3 = 0ULL;
        const ulonglong2* wbase = sW2 + k * (CF * 6);
        #pragma unroll
        for (int j = 0; j < CF; j++) {
            const ulonglong2* wr = wbase + j * 6;
            ulonglong2 t0 = wr[0], t1 = wr[1], t2 = wr[2];
            ull va = pmul(f2[0], t0.x);
            ull vb = pmul(f2[1], t0.y);
            va = pfma(f2[2], t1.x, va);
            vb = pfma(f2[3], t1.y, vb);
            va = pfma(f2[4], t2.x, va);
            vb = pfma(f2[5], t2.y, vb);
            ulonglong2 t3 = wr[3], t4 = wr[4];
            ull t10 = wr[5].x;
            va = pfma(f2[6], t3.x, va);
            vb = pfma(f2[7], t3.y, vb);
            va = pfma(f2[8], t4.x, va);
            vb = pfma(f2[9], t4.y, vb);
            va = pfma(f2[10], t10, va);
            ull v = padd(va, vb);
            o0  = pfma(pdup(ctx[0][j]), v, o0);   // static j -> register refs
            o1  = pfma(pdup(ctx[1][j]), v, o1);
            o2a = pfma(pdup(ctx[2][j]), v, o2a);
            o3  = pfma(pdup(ctx[3][j]), v, o3);
        }
        // residual fold: self feature k is still resident in myst[k]
        float xk = myst[k];
        float a, b;
        upk2(o0, a, b);  myst[0 * CF + k] = a + b + xk;
        upk2(o1, a, b);  myst[1 * CF + k] = a + b + xk;
        upk2(o2a, a, b); myst[2 * CF + k] = a + b + xk;
        upk2(o3, a, b);  myst[3 * CF + k] = a + b + xk;
    }
    __syncthreads();

    // ---- table-driven drain: pure smem->gmem copy, no div, no LDG ----
    const int Wr = W * 4;
    {   // out4: 64 px * 9 floats = 144 float4 per hi-res row
        const int QR = 144;
        for (int idx = tid; idx < TILE_H * 4 * QR; idx += NT) {
            int y = idx / QR;
            int q = idx - y * QR;
            int py = y >> 2;
            int base = py * (TILE_W * 89) + (((y & 3) == 3) ? 2 * CF : 0);
            ushort4 tb = *(const ushort4*)(tbl4 + q * 4);
            float4 v = make_float4(stg[base + tb.x], stg[base + tb.y],
                                   stg[base + tb.z], stg[base + tb.w]);
            int gy = ty0 * 4 + y;
            float4* dst = (float4*)(out + ((size_t)gy * Wr + (size_t)tx0 * 4) * 9);
            dst[q] = v;
        }
    }
    {   // out6: 64 px * 13 floats = 208 float4 per hi-res row
        const size_t N9 = (size_t)H * W * 16 * 9;
        const int QR = 208;
        for (int idx = tid; idx < TILE_H * 4 * QR; idx += NT) {
            int y = idx / QR;
            int q = idx - y * QR;
            int py = y >> 2;
            int base = py * (TILE_W * 89) + (((y & 3) == 3) ? 2 * CF : 0);
            ushort4 tb = *(const ushort4*)(tbl6 + q * 4);
            float4 v = make_float4(stg[base + tb.x], stg[base + tb.y],
                                   stg[base + tb.z], stg[base + tb.w]);
            int gy = ty0 * 4 + y;
            float4* dst = (float4*)(out + N9 + ((size_t)gy * Wr + (size_t)tx0 * 4) * 13);
            dst[q] = v;
        }
    }
}

extern "C" void kernel_launch(void* const* d_in, const int* in_sizes, int n_in,
                              void* d_out, int out_size) {
    const float* f4     = (const float*)d_in[0];
    const float* f6     = (const float*)d_in[1];
    const float* sh     = (const float*)d_in[2];
    const float* cg_agg = (const float*)d_in[3];
    const float* cg_tp  = (const float*)d_in[4];
    const float* w_agg  = (const float*)d_in[5];
    const float* w_tp   = (const float*)d_in[6];
    float* out = (float*)d_out;

    int HW = in_sizes[0] / 9;
    int W = (int)(sqrt((double)HW) + 0.5);
    int H = HW / W;

    prep_kernel<<<96, 128>>>(sh, cg_agg, cg_tp, w_agg, w_tp);

    // floats: sW 11616 + sK 4752 + stage 11392, then 1408 ushorts (704 floats)
    int smemB = (CF * CF * IPAD + NM * CF * KPAD + NT * 89 + 704) * (int)sizeof(float);
    cudaFuncSetAttribute(main_kernel, cudaFuncAttributeMaxDynamicSharedMemorySize, smemB);
    int nblocks = HW / NT;
    main_kernel<<<nblocks, NT, smemB>>>(f4, f6, out, H, W);
}